// round 12
// baseline (speedup 1.0000x reference)
#include <cuda_runtime.h>
#include <cuda_fp16.h>
#include <cstdint>

// Problem constants (fixed by the dataset)
#define B_DIM   64
#define C_DIM   4
#define RXD     64
#define E_DIM   512
#define P_DIM   4
#define OSIZE   256

#define L_TOT   (RXD * E_DIM)          // 32768
#define K_TOT   (P_DIM * L_TOT)        // 131072 (fan_in)
#define M_TOT   (B_DIM * C_DIM)        // 256 rows
#define N_TOT   OSIZE                  // 256

// GEMM tiling (fp16 mma.sync m16n8k16; fp16 mantissa == tf32 mantissa)
#define SPLITS  37
#define NCHUNK  4096                   // total BK-chunks = K_TOT / BK
#define CHUNK_Q 110                    // NCHUNK / SPLITS
#define CHUNK_R 26                     // NCHUNK % SPLITS  (first 26 splits get 111)
#define BM      128
#define BN      128
#define BK      32                     // K elements per stage
#define PADH    40                     // smem row stride in halves (80B; frag LDS conflict-free)
#define STAGES  3
#define STAGE_HALVES (2 * 128 * PADH)  // A(128xPADH) + B(128xPADH) = 10240 halves = 20KB
#define GEMM_SMEM (STAGES * STAGE_HALVES * 2)   // 61440 bytes

#define ROWS_PB 8                      // rows per prep block

// Scratch (device globals: allowed; no runtime allocation)
__device__ __half g_cat[M_TOT * K_TOT];                // 67 MB fp16 features
__device__ float  g_part[SPLITS * M_TOT * N_TOT];      // 9.7 MB split-K partials

// ---------------------------------------------------------------------------
// Kernel 1: build cat (fp16 output; masking logic unchanged)
// ---------------------------------------------------------------------------
__global__ __launch_bounds__(256)
void prep_kernel(const float* __restrict__ x,
                 const int*   __restrict__ rxd_perm,
                 const int*   __restrict__ e_idx,
                 const float* __restrict__ signs) {
    __shared__ float xs[ROWS_PB][E_DIM];
    __shared__ int   tidx[P_DIM * E_DIM];
    __shared__ float tsgn[P_DIM * E_DIM];

    const int rr  = blockIdx.x;
    const int rb  = blockIdx.y;
    const int tid = threadIdx.x;

#pragma unroll
    for (int u = 0; u < 8; u++) {
        const int j = tid + 256 * u;
        const int p = j >> 9, e = j & 511;
        tidx[j] = e_idx[e * P_DIM + p];
        tsgn[j] = signs[e * P_DIM + p];
    }

    const int rp = rxd_perm[rr];
#pragma unroll
    for (int u = 0; u < 4; u++) {
        const int j = tid + 256 * u;
        const int r = j >> 7;
        const int c = j & 127;
        const float* src = x + ((size_t)(rb * ROWS_PB + r) * RXD + rp) * E_DIM;
        ((float4*)xs[r])[c] = ((const float4*)src)[c];
    }
    __syncthreads();

    const int p     = tid >> 6;
    const int ebase = (tid & 63) << 3;
    const int jb    = p * E_DIM + ebase;

    int   ix[8]; float sg[8];
#pragma unroll
    for (int i = 0; i < 8; i++) { ix[i] = tidx[jb + i]; sg[i] = tsgn[jb + i]; }

    for (int r = 0; r < ROWS_PB; r++) {
        float v[8];
#pragma unroll
        for (int i = 0; i < 8; i++) v[i] = xs[r][ix[i]] * sg[i];

        float o[8];
        if (p == 0) {
#pragma unroll
            for (int i = 0; i < 8; i++) o[i] = v[i];
        } else if (p == 1) {
#pragma unroll
            for (int g = 0; g < 4; g++) {
                const float a = v[2*g], b = v[2*g + 1];
                if (b > a) { o[2*g] = 0.f; o[2*g+1] = b; }
                else       { o[2*g] = a;   o[2*g+1] = 0.f; }
            }
        } else if (p == 2) {
#pragma unroll
            for (int g = 0; g < 2; g++) {
                int idx = 0; float mx = v[4*g];
#pragma unroll
                for (int i = 1; i < 4; i++)
                    if (v[4*g + i] > mx) { mx = v[4*g + i]; idx = i; }
#pragma unroll
                for (int i = 0; i < 4; i++) o[4*g + i] = (i == idx) ? mx : 0.f;
            }
        } else {
            int idx = 0; float mx = v[0];
#pragma unroll
            for (int i = 1; i < 8; i++)
                if (v[i] > mx) { mx = v[i]; idx = i; }
#pragma unroll
            for (int i = 0; i < 8; i++) o[i] = (i == idx) ? mx : 0.f;
        }

        // Convert to fp16 (RN). fp16 mantissa == tf32 mantissa, so no
        // precision loss vs the validated tf32 pipeline.
        __half2 hp[4];
#pragma unroll
        for (int i = 0; i < 4; i++) hp[i] = __floats2half2_rn(o[2*i], o[2*i+1]);

        __half* dst = g_cat + (size_t)(rb * ROWS_PB + r) * K_TOT
                    + p * L_TOT + rr * E_DIM + ebase;
        *(uint4*)dst = *(uint4*)hp;   // 8 halves = 16B, aligned
    }
}

// ---------------------------------------------------------------------------
// Kernel 2: split-K FP16 GEMM via mma.sync.m16n8k16
//   A = g_cat (fp16, cp.async), B = W (f32 gmem -> fp16 smem in-flight)
// ---------------------------------------------------------------------------
__device__ __forceinline__ void cpasync16h(__half* s, const __half* g) {
    unsigned sa = (unsigned)__cvta_generic_to_shared(s);
    asm volatile("cp.async.cg.shared.global [%0], [%1], 16;" :: "r"(sa), "l"(g));
}

__global__ __launch_bounds__(256, 1)
void gemm_kernel(const float* __restrict__ W) {
    extern __shared__ __half smem[];   // STAGES x [ A(128xPADH) | B(128xPADH) ]

    const int tid = threadIdx.x;
    const int n0  = blockIdx.x * BN;
    const int m0  = blockIdx.y * BM;
    const int z   = blockIdx.z;

    // Uneven split: first CHUNK_R splits take CHUNK_Q+1 chunks.
    const int base  = z * CHUNK_Q + (z < CHUNK_R ? z : CHUNK_R);
    const int nIter = CHUNK_Q + (z < CHUNK_R ? 1 : 0);
    const int k00   = base * BK;

    // A cp.async mapping: 2 threads per row, 2x16B each.
    const int arow = tid >> 1;                 // 0..127
    const int ah   = (tid & 1) * 16;           // half-offset 0 / 16
    // B LDG mapping: 2 threads per row, 16 f32 each.
    const int brow = tid >> 1;
    const int bh   = (tid & 1) * 16;           // f32 offset 0 / 16

    auto loadA = [&](int slot, int s) {
        const int k0 = k00 + s * BK;
        __half* As = smem + slot * STAGE_HALVES;
        const __half* src = g_cat + (size_t)(m0 + arow) * K_TOT + k0 + ah;
        cpasync16h(&As[arow * PADH + ah],     src);
        cpasync16h(&As[arow * PADH + ah + 8], src + 8);
        asm volatile("cp.async.commit_group;");
    };
    auto fetchB = [&](int s, float4* f) {
        const int k0 = k00 + s * BK;
        const float* src = W + (size_t)(n0 + brow) * K_TOT + k0 + bh;
#pragma unroll
        for (int i = 0; i < 4; i++) f[i] = ((const float4*)src)[i];
    };
    auto storeB = [&](int slot, const float4* f) {
        __half* Bs = smem + slot * STAGE_HALVES + 128 * PADH;
        __half2 hb[8];
#pragma unroll
        for (int i = 0; i < 4; i++) {
            hb[2*i]   = __floats2half2_rn(f[i].x, f[i].y);
            hb[2*i+1] = __floats2half2_rn(f[i].z, f[i].w);
        }
        *(uint4*)&Bs[brow * PADH + bh]     = *(uint4*)&hb[0];
        *(uint4*)&Bs[brow * PADH + bh + 8] = *(uint4*)&hb[4];
    };

    const int warp = tid >> 5, lane = tid & 31;
    const int wm = warp >> 2;      // 0..1  (64 rows per warp)
    const int wn = warp & 3;       // 0..3  (32 cols per warp)
    const int ar = lane >> 2;      // 0..7
    const int ac = lane & 3;       // 0..3

    float acc[4][4][4];
#pragma unroll
    for (int i = 0; i < 4; i++)
#pragma unroll
        for (int j = 0; j < 4; j++)
#pragma unroll
            for (int q = 0; q < 4; q++) acc[i][j][q] = 0.f;

    // Prologue: stages 0 and 1 (B synchronously, A via cp.async)
    loadA(0, 0);
    loadA(1, 1);
    {
        float4 f[4];
        fetchB(0, f); storeB(0, f);
        fetchB(1, f); storeB(1, f);
    }
    __syncthreads();   // B stages 0,1 visible

    for (int it = 0; it < nIter; ++it) {
        float4 bfetch[4];
        const bool pf = (it + 2 < nIter);
        if (pf) {
            fetchB(it + 2, bfetch);            // LDG early; latency hidden by compute
            loadA((it + 2) % STAGES, it + 2);
        }
        if (pf)                     asm volatile("cp.async.wait_group 2;");
        else if (it + 1 < nIter)    asm volatile("cp.async.wait_group 1;");
        else                        asm volatile("cp.async.wait_group 0;");
        __syncthreads();   // A(it) landed; B(it) stored before prev sync

        const uint32_t* as32 = (const uint32_t*)(smem + (it % STAGES) * STAGE_HALVES);
        const uint32_t* bs32 = as32 + (128 * PADH) / 2;
        const int rowW = PADH / 2;   // 20 words per row
#pragma unroll
        for (int ks = 0; ks < 2; ks++) {       // 2 x K=16
            const int w0 = ks * 8 + ac;
            unsigned af[4][4];
#pragma unroll
            for (int mt = 0; mt < 4; mt++) {
                const int r = wm * 64 + mt * 16 + ar;
                af[mt][0] = as32[r       * rowW + w0];
                af[mt][1] = as32[(r + 8) * rowW + w0];
                af[mt][2] = as32[r       * rowW + w0 + 4];
                af[mt][3] = as32[(r + 8) * rowW + w0 + 4];
            }
            unsigned bf[4][2];
#pragma unroll
            for (int nt = 0; nt < 4; nt++) {
                const int n = wn * 32 + nt * 8 + ar;
                bf[nt][0] = bs32[n * rowW + w0];
                bf[nt][1] = bs32[n * rowW + w0 + 4];
            }
#pragma unroll
            for (int mt = 0; mt < 4; mt++)
#pragma unroll
                for (int nt = 0; nt < 4; nt++) {
                    asm volatile(
                        "mma.sync.aligned.m16n8k16.row.col.f32.f16.f16.f32 "
                        "{%0,%1,%2,%3}, {%4,%5,%6,%7}, {%8,%9}, {%0,%1,%2,%3};"
                        : "+f"(acc[mt][nt][0]), "+f"(acc[mt][nt][1]),
                          "+f"(acc[mt][nt][2]), "+f"(acc[mt][nt][3])
                        : "r"(af[mt][0]), "r"(af[mt][1]), "r"(af[mt][2]), "r"(af[mt][3]),
                          "r"(bf[nt][0]), "r"(bf[nt][1]));
                }
        }

        if (pf) storeB((it + 2) % STAGES, bfetch);   // slot (it+2)%3 != it%3
        __syncthreads();
    }

    // Epilogue: write partials (C fragment layout of m16n8)
    float* part = g_part + (size_t)z * (M_TOT * N_TOT);
#pragma unroll
    for (int mt = 0; mt < 4; mt++) {
        const int m = m0 + wm * 64 + mt * 16 + ar;
#pragma unroll
        for (int nt = 0; nt < 4; nt++) {
            const int n = n0 + wn * 32 + nt * 8 + 2 * ac;
            *(float2*)&part[(size_t)m * N_TOT + n]       = make_float2(acc[mt][nt][0], acc[mt][nt][1]);
            *(float2*)&part[(size_t)(m + 8) * N_TOT + n] = make_float2(acc[mt][nt][2], acc[mt][nt][3]);
        }
    }
}

// ---------------------------------------------------------------------------
// Kernel 3: deterministic split-K reduction + bias
// ---------------------------------------------------------------------------
__global__ void reduce_kernel(const float* __restrict__ bias, float* __restrict__ out) {
    const int m = blockIdx.x;
    const int n = threadIdx.x;
    float s = bias[n];
    const float* p = g_part + (size_t)m * N_TOT + n;
#pragma unroll
    for (int zz = 0; zz < SPLITS; zz++)
        s += p[(size_t)zz * (M_TOT * N_TOT)];
    out[(size_t)m * N_TOT + n] = s;
}

// ---------------------------------------------------------------------------
extern "C" void kernel_launch(void* const* d_in, const int* in_sizes, int n_in,
                              void* d_out, int out_size) {
    const float* x        = (const float*)d_in[0];
    const int*   rxd_perm = (const int*)  d_in[1];
    const int*   e_idx    = (const int*)  d_in[2];
    const float* signs    = (const float*)d_in[3];
    const float* W        = (const float*)d_in[4];
    const float* b        = (const float*)d_in[5];
    float* out = (float*)d_out;

    cudaFuncSetAttribute(gemm_kernel, cudaFuncAttributeMaxDynamicSharedMemorySize, GEMM_SMEM);

    prep_kernel<<<dim3(RXD, M_TOT / ROWS_PB), 256>>>(x, rxd_perm, e_idx, signs);
    gemm_kernel<<<dim3(N_TOT / BN, M_TOT / BM, SPLITS), 256, GEMM_SMEM>>>(W);
    reduce_kernel<<<M_TOT, N_TOT>>>(b, out);
}